// round 1
// baseline (speedup 1.0000x reference)
#include <cuda_runtime.h>

#define NB 16
#define NC 16
#define NP 512
#define ND 256
#define PD (NP*ND)            // 131072
#define BCPD (NB*NC*PD)       // 33554432

// Scratch (allocation-free rule: __device__ globals)
__device__ float g_ctx[BCPD];
__device__ float g_q[BCPD];
__device__ float g_k[BCPD];
__device__ float g_v[BCPD];
__device__ float g_scores[(size_t)NB*NC*NP*NP];   // 67108864 floats = 268MB

// ---------------------------------------------------------------------------
// context[b,c,p,d] = sum_c' aw[c',p,d]*query[b,c',p,d] - aw[c,p,d]*query[b,c,p,d]
// ---------------------------------------------------------------------------
__global__ void ctx_kernel(const float* __restrict__ query,
                           const float* __restrict__ aw)
{
    int idx = blockIdx.x * blockDim.x + threadIdx.x;   // over NB*PD/4
    int b   = idx / (PD/4);
    int pd  = idx - b*(PD/4);
    const float4* q4 = (const float4*)query;
    const float4* a4 = (const float4*)aw;
    float4 t[NC];
    float sx=0.f, sy=0.f, sz=0.f, sw=0.f;
#pragma unroll
    for (int c=0; c<NC; c++) {
        float4 qv = q4[(b*NC+c)*(PD/4)+pd];
        float4 av = a4[c*(PD/4)+pd];
        float4 m;
        m.x=av.x*qv.x; m.y=av.y*qv.y; m.z=av.z*qv.z; m.w=av.w*qv.w;
        t[c]=m; sx+=m.x; sy+=m.y; sz+=m.z; sw+=m.w;
    }
    float4* c4 = (float4*)g_ctx;
#pragma unroll
    for (int c=0; c<NC; c++) {
        float4 o;
        o.x=sx-t[c].x; o.y=sy-t[c].y; o.z=sz-t[c].z; o.w=sw-t[c].w;
        c4[(b*NC+c)*(PD/4)+pd]=o;
    }
}

// ---------------------------------------------------------------------------
// 128x128x8 SGEMM tile body (8x8 micro-tile, quadrant layout).
// ---------------------------------------------------------------------------
#define GEMM_COMPUTE_STEP(As, Bs)                                              \
    _Pragma("unroll")                                                          \
    for (int kk=0; kk<8; kk++) {                                               \
        float a[8], b[8];                                                      \
        *(float4*)(a)   = *(const float4*)&As[kk][ty*4];                       \
        *(float4*)(a+4) = *(const float4*)&As[kk][64+ty*4];                    \
        *(float4*)(b)   = *(const float4*)&Bs[kk][tx*4];                       \
        *(float4*)(b+4) = *(const float4*)&Bs[kk][64+tx*4];                    \
        _Pragma("unroll")                                                      \
        for (int i=0; i<8; i++)                                                \
            _Pragma("unroll")                                                  \
            for (int j=0; j<8; j++)                                            \
                acc[i][j] += a[i]*b[j];                                        \
    }

// ---------------------------------------------------------------------------
// Projections: out = relu(X @ W + bias) [* 1/sqrt(D) for q]
// which 0=q (X=query), 1=k (X=context), 2=v (X=context)
// ---------------------------------------------------------------------------
__global__ __launch_bounds__(256) void proj_kernel(
    const float* __restrict__ query,
    const float* __restrict__ wq, const float* __restrict__ wk, const float* __restrict__ wv,
    const float* __restrict__ bq, const float* __restrict__ bk, const float* __restrict__ bv)
{
    __shared__ float As[8][128];
    __shared__ float Bs[8][128];
    int z     = blockIdx.z;
    int which = z / (NB*NC);
    int bc    = z - which*(NB*NC);
    int cyc   = bc & (NC-1);
    const float* A    = (which==0 ? query : g_ctx) + (size_t)bc*PD;
    const float* W    = (which==0 ? wq : (which==1 ? wk : wv)) + (size_t)cyc*ND*ND;
    const float* bias = (which==0 ? bq : (which==1 ? bk : bv)) + cyc*ND;
    float* outp       = (which==0 ? g_q : (which==1 ? g_k : g_v)) + (size_t)bc*PD;
    float scale = (which==0) ? 0.0625f : 1.0f;

    int m0 = blockIdx.y*128, n0 = blockIdx.x*128;
    int tid = threadIdx.x;
    int arow = tid>>1,  acol = (tid&1)*4;
    int brow = tid>>5,  bcol = (tid&31)*4;
    int tx = tid&15, ty = tid>>4;

    float acc[8][8];
#pragma unroll
    for (int i=0;i<8;i++)
#pragma unroll
        for (int j=0;j<8;j++) acc[i][j]=0.f;

    for (int k0=0; k0<ND; k0+=8) {
        float4 av = *(const float4*)(A + (size_t)(m0+arow)*ND + k0 + acol);
        As[acol+0][arow]=av.x; As[acol+1][arow]=av.y;
        As[acol+2][arow]=av.z; As[acol+3][arow]=av.w;
        *(float4*)&Bs[brow][bcol] = *(const float4*)(W + (size_t)(k0+brow)*ND + n0 + bcol);
        __syncthreads();
        GEMM_COMPUTE_STEP(As, Bs)
        __syncthreads();
    }

#pragma unroll
    for (int i=0;i<8;i++) {
        int gm = m0 + ((i<4) ? (ty*4+i) : (64+ty*4+i-4));
#pragma unroll
        for (int jj=0;jj<2;jj++) {
            int gn = n0 + (jj==0 ? tx*4 : 64+tx*4);
            float4 o;
            o.x = fmaxf(acc[i][jj*4+0] + bias[gn+0], 0.f)*scale;
            o.y = fmaxf(acc[i][jj*4+1] + bias[gn+1], 0.f)*scale;
            o.z = fmaxf(acc[i][jj*4+2] + bias[gn+2], 0.f)*scale;
            o.w = fmaxf(acc[i][jj*4+3] + bias[gn+3], 0.f)*scale;
            *(float4*)(outp + (size_t)gm*ND + gn) = o;
        }
    }
}

// ---------------------------------------------------------------------------
// scores = q @ k^T  (per b,c: 512x512, K=256)
// ---------------------------------------------------------------------------
__global__ __launch_bounds__(256) void scores_kernel()
{
    __shared__ float As[8][128];
    __shared__ float Bs[8][128];
    int bc = blockIdx.z;
    const float* A  = g_q + (size_t)bc*PD;
    const float* Bm = g_k + (size_t)bc*PD;
    float* outp = g_scores + (size_t)bc*NP*NP;

    int m0 = blockIdx.y*128, n0 = blockIdx.x*128;
    int tid = threadIdx.x;
    int arow = tid>>1, acol = (tid&1)*4;
    int tx = tid&15, ty = tid>>4;

    float acc[8][8];
#pragma unroll
    for (int i=0;i<8;i++)
#pragma unroll
        for (int j=0;j<8;j++) acc[i][j]=0.f;

    for (int k0=0; k0<ND; k0+=8) {
        float4 av = *(const float4*)(A  + (size_t)(m0+arow)*ND + k0 + acol);
        As[acol+0][arow]=av.x; As[acol+1][arow]=av.y;
        As[acol+2][arow]=av.z; As[acol+3][arow]=av.w;
        float4 bv = *(const float4*)(Bm + (size_t)(n0+arow)*ND + k0 + acol);
        Bs[acol+0][arow]=bv.x; Bs[acol+1][arow]=bv.y;
        Bs[acol+2][arow]=bv.z; Bs[acol+3][arow]=bv.w;
        __syncthreads();
        GEMM_COMPUTE_STEP(As, Bs)
        __syncthreads();
    }

#pragma unroll
    for (int i=0;i<8;i++) {
        int gm = m0 + ((i<4) ? (ty*4+i) : (64+ty*4+i-4));
#pragma unroll
        for (int jj=0;jj<2;jj++) {
            int gn = n0 + (jj==0 ? tx*4 : 64+tx*4);
            float4 o;
            o.x=acc[i][jj*4+0]; o.y=acc[i][jj*4+1];
            o.z=acc[i][jj*4+2]; o.w=acc[i][jj*4+3];
            *(float4*)(outp + (size_t)gm*NP + gn) = o;
        }
    }
}

// ---------------------------------------------------------------------------
// row-wise softmax over 512 columns (one warp per row)
// ---------------------------------------------------------------------------
__global__ void softmax_kernel()
{
    size_t row = (size_t)blockIdx.x*8 + threadIdx.y;  // over NB*NC*NP
    float4* r = (float4*)g_scores + row*(NP/4);
    int lane = threadIdx.x;
    float4 v[4];
    float mx = -1e30f;
#pragma unroll
    for (int i=0;i<4;i++) {
        v[i] = r[lane + 32*i];
        mx = fmaxf(mx, fmaxf(fmaxf(v[i].x,v[i].y), fmaxf(v[i].z,v[i].w)));
    }
#pragma unroll
    for (int o=16;o>0;o>>=1) mx = fmaxf(mx, __shfl_xor_sync(0xffffffffu, mx, o));
    float sum = 0.f;
#pragma unroll
    for (int i=0;i<4;i++) {
        v[i].x = __expf(v[i].x-mx); v[i].y = __expf(v[i].y-mx);
        v[i].z = __expf(v[i].z-mx); v[i].w = __expf(v[i].w-mx);
        sum += v[i].x+v[i].y+v[i].z+v[i].w;
    }
#pragma unroll
    for (int o=16;o>0;o>>=1) sum += __shfl_xor_sync(0xffffffffu, sum, o);
    float inv = 1.f/sum;
#pragma unroll
    for (int i=0;i<4;i++) {
        v[i].x*=inv; v[i].y*=inv; v[i].z*=inv; v[i].w*=inv;
        r[lane + 32*i] = v[i];
    }
}

// ---------------------------------------------------------------------------
// out = attn @ v   (per b,c: (512x512)@(512x256))
// ---------------------------------------------------------------------------
__global__ __launch_bounds__(256) void out_kernel(float* __restrict__ op)
{
    __shared__ float As[8][128];
    __shared__ float Bs[8][128];
    int bc = blockIdx.z;
    const float* A  = g_scores + (size_t)bc*NP*NP;   // lda = NP
    const float* Bm = g_v + (size_t)bc*PD;           // ldb = ND
    float* outp = op + (size_t)bc*PD;

    int m0 = blockIdx.y*128, n0 = blockIdx.x*128;
    int tid = threadIdx.x;
    int arow = tid>>1, acol = (tid&1)*4;
    int brow = tid>>5, bcol = (tid&31)*4;
    int tx = tid&15, ty = tid>>4;

    float acc[8][8];
#pragma unroll
    for (int i=0;i<8;i++)
#pragma unroll
        for (int j=0;j<8;j++) acc[i][j]=0.f;

    for (int k0=0; k0<NP; k0+=8) {
        float4 av = *(const float4*)(A + (size_t)(m0+arow)*NP + k0 + acol);
        As[acol+0][arow]=av.x; As[acol+1][arow]=av.y;
        As[acol+2][arow]=av.z; As[acol+3][arow]=av.w;
        *(float4*)&Bs[brow][bcol] = *(const float4*)(Bm + (size_t)(k0+brow)*ND + n0 + bcol);
        __syncthreads();
        GEMM_COMPUTE_STEP(As, Bs)
        __syncthreads();
    }

#pragma unroll
    for (int i=0;i<8;i++) {
        int gm = m0 + ((i<4) ? (ty*4+i) : (64+ty*4+i-4));
#pragma unroll
        for (int jj=0;jj<2;jj++) {
            int gn = n0 + (jj==0 ? tx*4 : 64+tx*4);
            float4 o;
            o.x=acc[i][jj*4+0]; o.y=acc[i][jj*4+1];
            o.z=acc[i][jj*4+2]; o.w=acc[i][jj*4+3];
            *(float4*)(outp + (size_t)gm*ND + gn) = o;
        }
    }
}

// ---------------------------------------------------------------------------
extern "C" void kernel_launch(void* const* d_in, const int* in_sizes, int n_in,
                              void* d_out, int out_size)
{
    const float* query = (const float*)d_in[0];
    const float* aw    = (const float*)d_in[1];
    const float* wq    = (const float*)d_in[2];
    const float* wk    = (const float*)d_in[3];
    const float* wv    = (const float*)d_in[4];
    const float* bq    = (const float*)d_in[5];
    const float* bk    = (const float*)d_in[6];
    const float* bv    = (const float*)d_in[7];
    float* out = (float*)d_out;

    ctx_kernel<<<(NB*PD/4)/256, 256>>>(query, aw);
    proj_kernel<<<dim3(ND/128, NP/128, 3*NB*NC), 256>>>(query, wq, wk, wv, bq, bk, bv);
    scores_kernel<<<dim3(NP/128, NP/128, NB*NC), 256>>>();
    softmax_kernel<<<(NB*NC*NP)/8, dim3(32,8)>>>();
    out_kernel<<<dim3(ND/128, NP/128, NB*NC), 256>>>(out);
}

// round 12
// speedup vs baseline: 3.2998x; 3.2998x over previous
#include <cuda_runtime.h>
#include <cstdint>

#define NB 16
#define NC 16
#define NP 512
#define ND 256
#define PD (NP*ND)            // 131072
#define BCPD (NB*NC*PD)       // 33554432

#define BK  16
#define AST 20                // padded smem row stride (floats)

// ---------------- scratch (__device__ globals; allocation-free rule) -------
__device__ __align__(128) float g_ctx[BCPD];
__device__ __align__(128) float g_q[BCPD];
__device__ __align__(128) float g_k[BCPD];
__device__ __align__(128) float g_v[BCPD];
__device__ __align__(128) float g_vT[BCPD];
__device__ __align__(128) float g_wT[3*NC*ND*ND];
__device__ __align__(128) float g_scores[(size_t)NB*NC*NP*NP];

// ---------------------------------------------------------------------------
// tf32 helpers (base sm_103 — NO tcgen05, NO 'a'-features)
// ---------------------------------------------------------------------------
__device__ __forceinline__ float to_tf32(float x) {
    float y;
    asm("cvt.rna.tf32.f32 %0, %1;" : "=f"(y) : "f"(x));
    return y;
}
__device__ __forceinline__ float4 to_tf32_4(float4 v) {
    v.x = to_tf32(v.x); v.y = to_tf32(v.y);
    v.z = to_tf32(v.z); v.w = to_tf32(v.w);
    return v;
}
__device__ __forceinline__ void mma8(float* c, const float* a, float b0, float b1) {
    asm volatile(
        "mma.sync.aligned.m16n8k8.row.col.f32.tf32.tf32.f32 "
        "{%0,%1,%2,%3}, {%4,%5,%6,%7}, {%8,%9}, {%0,%1,%2,%3};"
        : "+f"(c[0]), "+f"(c[1]), "+f"(c[2]), "+f"(c[3])
        : "r"(__float_as_uint(a[0])), "r"(__float_as_uint(a[1])),
          "r"(__float_as_uint(a[2])), "r"(__float_as_uint(a[3])),
          "r"(__float_as_uint(b0)), "r"(__float_as_uint(b1)));
}

// ---------------------------------------------------------------------------
// context kernel
// ---------------------------------------------------------------------------
__global__ void ctx_kernel(const float* __restrict__ query,
                           const float* __restrict__ aw)
{
    int idx = blockIdx.x * blockDim.x + threadIdx.x;
    int b   = idx / (PD/4);
    int pd  = idx - b*(PD/4);
    const float4* q4 = (const float4*)query;
    const float4* a4 = (const float4*)aw;
    float4 t[NC];
    float sx=0.f, sy=0.f, sz=0.f, sw=0.f;
#pragma unroll
    for (int c=0; c<NC; c++) {
        float4 qv = q4[(b*NC+c)*(PD/4)+pd];
        float4 av = a4[c*(PD/4)+pd];
        float4 m;
        m.x=av.x*qv.x; m.y=av.y*qv.y; m.z=av.z*qv.z; m.w=av.w*qv.w;
        t[c]=m; sx+=m.x; sy+=m.y; sz+=m.z; sw+=m.w;
    }
    float4* c4 = (float4*)g_ctx;
#pragma unroll
    for (int c=0; c<NC; c++) {
        float4 o;
        o.x=sx-t[c].x; o.y=sy-t[c].y; o.z=sz-t[c].z; o.w=sw-t[c].w;
        c4[(b*NC+c)*(PD/4)+pd]=o;
    }
}

// ---------------------------------------------------------------------------
// weight transpose: g_wT[which][c][n][k] = W_which[c][k][n]
// ---------------------------------------------------------------------------
__global__ void transpose_w(const float* __restrict__ wq,
                            const float* __restrict__ wk,
                            const float* __restrict__ wv)
{
    __shared__ float t[32][33];
    int z = blockIdx.z;                 // 0..47
    int which = z >> 4, c = z & 15;
    const float* W = (which==0 ? wq : (which==1 ? wk : wv)) + (size_t)c*ND*ND;
    float* WT = g_wT + ((size_t)which*NC + c)*ND*ND;
    int k0 = blockIdx.x*32, n0 = blockIdx.y*32;
    int tx = threadIdx.x, ty = threadIdx.y;
#pragma unroll
    for (int r=ty; r<32; r+=8) t[r][tx] = W[(size_t)(k0+r)*ND + n0+tx];
    __syncthreads();
#pragma unroll
    for (int r=ty; r<32; r+=8) WT[(size_t)(n0+r)*ND + k0+tx] = t[tx][r];
}

// ---------------------------------------------------------------------------
// v transpose: g_vT[bc][e][q] = g_v[bc][q][e]
// ---------------------------------------------------------------------------
__global__ void transpose_v()
{
    __shared__ float t[32][33];
    int bc = blockIdx.z;
    const float* V = g_v + (size_t)bc*PD;
    float* VT = g_vT + (size_t)bc*PD;
    int q0 = blockIdx.x*32, e0 = blockIdx.y*32;
    int tx = threadIdx.x, ty = threadIdx.y;
#pragma unroll
    for (int r=ty; r<32; r+=8) t[r][tx] = V[(size_t)(q0+r)*ND + e0+tx];
    __syncthreads();
#pragma unroll
    for (int r=ty; r<32; r+=8) VT[(size_t)(e0+r)*NP + q0+tx] = t[tx][r];
}

// ---------------------------------------------------------------------------
// tf32 mma.sync GEMM: D(M,N) = A(M,K) @ B(N,K)^T, both K-major.
// Tile 128x128, BK=16, double-buffered padded smem, 8 warps:
// warp grid 4(M)x2(N), warp tile 32x64 of m16n8k8 fragments.
// ---------------------------------------------------------------------------
__global__ __launch_bounds__(256)
void mma_gemm(const float* __restrict__ extA, float* __restrict__ extD,
              int Asel, int Bsel, int Dsel,
              int lda, int ldb, int ldd, int nkt,
              const float* __restrict__ bias0, float scale, int hasBias)
{
    __shared__ float As[2][128*AST];
    __shared__ float Bs[2][128*AST];

    int tid = threadIdx.x;
    int warp = tid >> 5, lane = tid & 31;
    int gid = lane >> 2, tig = lane & 3;
    int wm = warp & 3, wn = warp >> 2;
    int z = blockIdx.z;

    const float* A;
    switch (Asel) {
        case 0: A = extA + (size_t)z*PD; break;
        case 1: A = g_ctx + (size_t)z*PD; break;
        case 2: A = g_q + (size_t)z*PD; break;
        default: A = g_scores + (size_t)z*NP*NP; break;
    }
    const float* B;
    switch (Bsel) {
        case 0: B = g_wT + ((size_t)0*NC + (z&15))*ND*ND; break;
        case 1: B = g_wT + ((size_t)1*NC + (z&15))*ND*ND; break;
        case 2: B = g_wT + ((size_t)2*NC + (z&15))*ND*ND; break;
        case 3: B = g_k + (size_t)z*PD; break;
        default: B = g_vT + (size_t)z*PD; break;
    }
    float* D;
    switch (Dsel) {
        case 0: D = g_q + (size_t)z*PD; break;
        case 1: D = g_k + (size_t)z*PD; break;
        case 2: D = g_v + (size_t)z*PD; break;
        case 3: D = g_scores + (size_t)z*NP*NP; break;
        default: D = extD + (size_t)z*PD; break;
    }
    const float* bias = hasBias ? (bias0 + (size_t)(z&15)*ND) : nullptr;

    int m0 = blockIdx.y*128, n0 = blockIdx.x*128;

    float acc[2][8][4];
#pragma unroll
    for (int mi=0; mi<2; mi++)
#pragma unroll
        for (int ni=0; ni<8; ni++)
#pragma unroll
            for (int j=0; j<4; j++) acc[mi][ni][j] = 0.f;

    // thread's gmem-load coords: 128 rows x 4 float4 per row = 512 f4, 2/thread
    int r0 = tid >> 2,          c40 = (tid & 3);          // f4 idx tid
    int r1 = (tid + 256) >> 2,  c41 = ((tid + 256) & 3);  // f4 idx tid+256

    // preload chunk 0
    {
        float4 a0 = to_tf32_4(*(const float4*)(A + (size_t)(m0+r0)*lda + c40*4));
        float4 a1 = to_tf32_4(*(const float4*)(A + (size_t)(m0+r1)*lda + c41*4));
        float4 b0 = to_tf32_4(*(const float4*)(B + (size_t)(n0+r0)*ldb + c40*4));
        float4 b1 = to_tf32_4(*(const float4*)(B + (size_t)(n0+r1)*ldb + c41*4));
        *(float4*)&As[0][r0*AST + c40*4] = a0;
        *(float4*)&As[0][r1*AST + c41*4] = a1;
        *(float4*)&Bs[0][r0*AST + c40*4] = b0;
        *(float4*)&Bs[0][r1*AST + c41*4] = b1;
    }
    __syncthreads();

    for (int kt = 0; kt < nkt; kt++) {
        int buf = kt & 1;
        float4 pa0, pa1, pb0, pb1;
        if (kt + 1 < nkt) {
            int k0 = (kt+1)*BK;
            pa0 = to_tf32_4(*(const float4*)(A + (size_t)(m0+r0)*lda + k0 + c40*4));
            pa1 = to_tf32_4(*(const float4*)(A + (size_t)(m0+r1)*lda + k0 + c41*4));
            pb0 = to_tf32_4(*(const float4*)(B + (size_t)(n0+r0)*ldb + k0 + c40*4));
            pb1 = to_tf32_4(*(const float4*)(B + (size_t)(n0+r1)*ldb + k0 + c41*4));
        }

        // compute on buf: 2 k-steps of 8
#pragma unroll
        for (int ks = 0; ks < 2; ks++) {
            int kk = ks*8;
            float a[2][4];
#pragma unroll
            for (int mi=0; mi<2; mi++) {
                int rb = wm*32 + mi*16 + gid;
                a[mi][0] = As[buf][rb*AST + kk + tig];
                a[mi][1] = As[buf][(rb+8)*AST + kk + tig];
                a[mi][2] = As[buf][rb*AST + kk + tig + 4];
                a[mi][3] = As[buf][(rb+8)*AST + kk + tig + 4];
            }
#pragma unroll
            for (int ni=0; ni<8; ni++) {
                int nb = wn*64 + ni*8 + gid;
                float b0 = Bs[buf][nb*AST + kk + tig];
                float b1 = Bs[buf][nb*AST + kk + tig + 4];
                mma8(acc[0][ni], a[0], b0, b1);
                mma8(acc[1][ni], a[1], b0, b1);
            }
        }

        if (kt + 1 < nkt) {
            int nbuf = buf ^ 1;
            *(float4*)&As[nbuf][r0*AST + c40*4] = pa0;
            *(float4*)&As[nbuf][r1*AST + c41*4] = pa1;
            *(float4*)&Bs[nbuf][r0*AST + c40*4] = pb0;
            *(float4*)&Bs[nbuf][r1*AST + c41*4] = pb1;
            __syncthreads();
        }
    }

    // epilogue
#pragma unroll
    for (int mi=0; mi<2; mi++) {
        int rr = m0 + wm*32 + mi*16 + gid;
#pragma unroll
        for (int ni=0; ni<8; ni++) {
            int cc = n0 + wn*64 + ni*8 + 2*tig;
            float v0 = acc[mi][ni][0], v1 = acc[mi][ni][1];
            float v2 = acc[mi][ni][2], v3 = acc[mi][ni][3];
            if (hasBias) {
                float bb0 = __ldg(bias + cc), bb1 = __ldg(bias + cc + 1);
                v0 = fmaxf(v0 + bb0, 0.f)*scale;
                v1 = fmaxf(v1 + bb1, 0.f)*scale;
                v2 = fmaxf(v2 + bb0, 0.f)*scale;
                v3 = fmaxf(v3 + bb1, 0.f)*scale;
            }
            *(float2*)(D + (size_t)rr*ldd + cc)     = make_float2(v0, v1);
            *(float2*)(D + (size_t)(rr+8)*ldd + cc) = make_float2(v2, v3);
        }
    }
}

// ---------------------------------------------------------------------------
// softmax
// ---------------------------------------------------------------------------
__global__ void softmax_kernel()
{
    size_t row = (size_t)blockIdx.x*8 + threadIdx.y;
    float4* r = (float4*)g_scores + row*(NP/4);
    int lane = threadIdx.x;
    float4 v[4];
    float mx = -1e30f;
#pragma unroll
    for (int i=0;i<4;i++) {
        v[i] = r[lane + 32*i];
        mx = fmaxf(mx, fmaxf(fmaxf(v[i].x,v[i].y), fmaxf(v[i].z,v[i].w)));
    }
#pragma unroll
    for (int o=16;o>0;o>>=1) mx = fmaxf(mx, __shfl_xor_sync(0xffffffffu, mx, o));
    float sum = 0.f;
#pragma unroll
    for (int i=0;i<4;i++) {
        v[i].x = __expf(v[i].x-mx); v[i].y = __expf(v[i].y-mx);
        v[i].z = __expf(v[i].z-mx); v[i].w = __expf(v[i].w-mx);
        sum += v[i].x+v[i].y+v[i].z+v[i].w;
    }
#pragma unroll
    for (int o=16;o>0;o>>=1) sum += __shfl_xor_sync(0xffffffffu, sum, o);
    float inv = 1.f/sum;
#pragma unroll
    for (int i=0;i<4;i++) {
        v[i].x*=inv; v[i].y*=inv; v[i].z*=inv; v[i].w*=inv;
        r[lane + 32*i] = v[i];
    }
}

// ---------------------------------------------------------------------------
extern "C" void kernel_launch(void* const* d_in, const int* in_sizes, int n_in,
                              void* d_out, int out_size)
{
    const float* query = (const float*)d_in[0];
    const float* aw    = (const float*)d_in[1];
    const float* wq    = (const float*)d_in[2];
    const float* wk    = (const float*)d_in[3];
    const float* wv    = (const float*)d_in[4];
    const float* bq    = (const float*)d_in[5];
    const float* bk    = (const float*)d_in[6];
    const float* bv    = (const float*)d_in[7];
    float* out = (float*)d_out;

    transpose_w<<<dim3(8,8,48), dim3(32,8)>>>(wq, wk, wv);
    ctx_kernel<<<(NB*PD/4)/256, 256>>>(query, aw);

    // projections: M=512 N=256 K=256  (nkt = 256/16 = 16)
    mma_gemm<<<dim3(2,4,NB*NC), 256>>>(query, nullptr, 0, 0, 0,
                                       ND, ND, ND, 16, bq, 0.0625f, 1);
    mma_gemm<<<dim3(2,4,NB*NC), 256>>>(nullptr, nullptr, 1, 1, 1,
                                       ND, ND, ND, 16, bk, 1.0f, 1);
    mma_gemm<<<dim3(2,4,NB*NC), 256>>>(nullptr, nullptr, 1, 2, 2,
                                       ND, ND, ND, 16, bv, 1.0f, 1);

    transpose_v<<<dim3(16,8,NB*NC), dim3(32,8)>>>();

    // scores: M=512 N=512 K=256
    mma_gemm<<<dim3(4,4,NB*NC), 256>>>(nullptr, nullptr, 2, 3, 3,
                                       ND, ND, NP, 16, nullptr, 1.0f, 0);

    softmax_kernel<<<(NB*NC*NP)/8, dim3(32,8)>>>();

    // out: M=512 N=256 K=512  (nkt = 512/16 = 32)
    mma_gemm<<<dim3(2,4,NB*NC), 256>>>(nullptr, out, 3, 4, 4,
                                       NP, NP, ND, 32, nullptr, 1.0f, 0);
}